// round 1
// baseline (speedup 1.0000x reference)
#include <cuda_runtime.h>
#include <math.h>

#define BB 2
#define SS 2048
#define DD 1024
#define HH 16
#define DH 64

// Scratch: q,k,v in [B,H,S,DH], context in [B,S,H*DH]
__device__ float g_q[BB*HH*SS*DH];
__device__ float g_k[BB*HH*SS*DH];
__device__ float g_v[BB*HH*SS*DH];
__device__ float g_ctx[(size_t)BB*SS*HH*DH];

// ---------------------------------------------------------------------------
// NT GEMM core: C[128,128] += A[128,K] * B[128,K]^T, A/B row-major stride lda/ldb.
// 256 threads, 8x8 microtile per thread. K must be a multiple of 16.
// ---------------------------------------------------------------------------
__device__ __forceinline__ void gemm_nt_tile(
    const float* __restrict__ A, int lda,
    const float* __restrict__ B, int ldb,
    int kTotal, float acc[8][8])
{
    __shared__ __align__(16) float As[16][132];
    __shared__ __align__(16) float Bs[16][132];
    const int tid = threadIdx.x;
    const int tx = tid & 15;
    const int ty = tid >> 4;
    for (int k0 = 0; k0 < kTotal; k0 += 16) {
        #pragma unroll
        for (int i = 0; i < 2; i++) {
            int f = tid + i * 256;       // float4 index in 128x16 tile
            int r = f >> 2;              // row 0..127
            int c = (f & 3) << 2;        // col 0,4,8,12
            float4 va = *(const float4*)(A + (size_t)r * lda + k0 + c);
            As[c+0][r] = va.x; As[c+1][r] = va.y; As[c+2][r] = va.z; As[c+3][r] = va.w;
            float4 vb = *(const float4*)(B + (size_t)r * ldb + k0 + c);
            Bs[c+0][r] = vb.x; Bs[c+1][r] = vb.y; Bs[c+2][r] = vb.z; Bs[c+3][r] = vb.w;
        }
        __syncthreads();
        #pragma unroll
        for (int kk = 0; kk < 16; kk++) {
            float a[8], b[8];
            *(float4*)&a[0] = *(const float4*)&As[kk][ty*8];
            *(float4*)&a[4] = *(const float4*)&As[kk][ty*8+4];
            *(float4*)&b[0] = *(const float4*)&Bs[kk][tx*8];
            *(float4*)&b[4] = *(const float4*)&Bs[kk][tx*8+4];
            #pragma unroll
            for (int i = 0; i < 8; i++)
                #pragma unroll
                for (int j = 0; j < 8; j++)
                    acc[i][j] = fmaf(a[i], b[j], acc[i][j]);
        }
        __syncthreads();
    }
}

// ---------------------------------------------------------------------------
// QKV projections: Y = X @ W^T + b, scattered to [B,H,S,DH]. grid.z selects q/k/v.
// ---------------------------------------------------------------------------
__global__ void qkv_proj_kernel(
    const float* __restrict__ Qin, const float* __restrict__ Kin, const float* __restrict__ Vin,
    const float* __restrict__ Wq, const float* __restrict__ bq,
    const float* __restrict__ Wk, const float* __restrict__ bk,
    const float* __restrict__ Wv, const float* __restrict__ bv)
{
    const int z = blockIdx.z;
    const float* X    = (z == 0) ? Qin : (z == 1) ? Kin : Vin;
    const float* W    = (z == 0) ? Wq  : (z == 1) ? Wk  : Wv;
    const float* bias = (z == 0) ? bq  : (z == 1) ? bk  : bv;
    float* out        = (z == 0) ? g_q : (z == 1) ? g_k : g_v;

    const int rowBase = blockIdx.y * 128;   // m in [0, B*S)
    const int colBase = blockIdx.x * 128;   // n in [0, H*DH)
    float acc[8][8] = {};
    gemm_nt_tile(X + (size_t)rowBase * DD, DD, W + (size_t)colBase * DD, DD, DD, acc);

    const int tx = threadIdx.x & 15, ty = threadIdx.x >> 4;
    #pragma unroll
    for (int i = 0; i < 8; i++) {
        int m = rowBase + ty * 8 + i;
        int b = m >> 11;            // /S
        int s = m & (SS - 1);
        #pragma unroll
        for (int j = 0; j < 8; j++) {
            int n = colBase + tx * 8 + j;
            int h = n >> 6, dh = n & 63;
            out[((((size_t)b * HH + h) * SS + s) << 6) + dh] = acc[i][j] + bias[n];
        }
    }
}

// ---------------------------------------------------------------------------
// Scores: S = q @ k^T * 0.125 into attn_prob buffer [B,H,S,S].
// Fully masked (strictly upper) 128x128 blocks skipped entirely.
// ---------------------------------------------------------------------------
__global__ void score_kernel(float* __restrict__ scores)
{
    const int bh = blockIdx.z;
    const int rowBase = blockIdx.y * 128;
    const int colBase = blockIdx.x * 128;
    if (colBase > rowBase + 127) return;   // uniform per block

    const float* q = g_q + (size_t)bh * SS * DH;
    const float* k = g_k + (size_t)bh * SS * DH;
    float acc[8][8] = {};
    gemm_nt_tile(q + (size_t)rowBase * DH, DH, k + (size_t)colBase * DH, DH, DH, acc);

    float* outp = scores + (size_t)bh * SS * SS;
    const int tx = threadIdx.x & 15, ty = threadIdx.x >> 4;
    #pragma unroll
    for (int i = 0; i < 8; i++) {
        size_t ro = (size_t)(rowBase + ty * 8 + i) * SS;
        #pragma unroll
        for (int j = 0; j < 8; j++)
            outp[ro + colBase + tx * 8 + j] = acc[i][j] * 0.125f;
    }
}

// ---------------------------------------------------------------------------
// Row softmax in place; masked tail (col > row) written as exact 0.
// One 256-thread block per row of 2048.
// ---------------------------------------------------------------------------
__global__ void softmax_kernel(float* __restrict__ sc)
{
    const int r = blockIdx.x;          // [0, B*H*S)
    const int qi = r & (SS - 1);
    const int valid = qi + 1;
    float* row = sc + (size_t)r * SS;
    const int tid = threadIdx.x;
    const int warp = tid >> 5, lane = tid & 31;
    __shared__ float red[8];

    float v[8];
    float m = -3.4e38f;
    #pragma unroll
    for (int i = 0; i < 8; i++) {
        int idx = tid + i * 256;
        v[i] = -3.4e38f;
        if (idx < valid) { v[i] = row[idx]; m = fmaxf(m, v[i]); }
    }
    #pragma unroll
    for (int o = 16; o > 0; o >>= 1) m = fmaxf(m, __shfl_xor_sync(0xffffffffu, m, o));
    if (lane == 0) red[warp] = m;
    __syncthreads();
    float mm = (lane < 8) ? red[lane] : -3.4e38f;
    #pragma unroll
    for (int o = 4; o > 0; o >>= 1) mm = fmaxf(mm, __shfl_xor_sync(0xffffffffu, mm, o));
    mm = __shfl_sync(0xffffffffu, mm, 0);
    __syncthreads();   // red reads done before reuse

    float s = 0.f;
    #pragma unroll
    for (int i = 0; i < 8; i++) {
        int idx = tid + i * 256;
        if (idx < valid) { v[i] = __expf(v[i] - mm); s += v[i]; }
    }
    #pragma unroll
    for (int o = 16; o > 0; o >>= 1) s += __shfl_xor_sync(0xffffffffu, s, o);
    if (lane == 0) red[warp] = s;
    __syncthreads();
    float ss = (lane < 8) ? red[lane] : 0.f;
    #pragma unroll
    for (int o = 4; o > 0; o >>= 1) ss += __shfl_xor_sync(0xffffffffu, ss, o);
    ss = __shfl_sync(0xffffffffu, ss, 0);

    const float inv = 1.0f / ss;
    #pragma unroll
    for (int i = 0; i < 8; i++) {
        int idx = tid + i * 256;
        row[idx] = (idx < valid) ? v[i] * inv : 0.0f;
    }
}

// ---------------------------------------------------------------------------
// Context: C[128,64] = P[128,K] @ V[K,64]; causal -> K loop stops at rowBase+128.
// Output into g_ctx [B,S,H*DH].
// ---------------------------------------------------------------------------
__global__ void context_kernel(const float* __restrict__ scores)
{
    const int bh = blockIdx.z;
    const int rowBase = blockIdx.x * 128;
    const float* P  = scores + (size_t)bh * SS * SS;
    const float* Vm = g_v + (size_t)bh * SS * DH;
    const int kTotal = rowBase + 128;       // cols beyond are exact zeros

    __shared__ __align__(16) float Ps[16][132];
    __shared__ __align__(16) float Vs[16][64];
    const int tid = threadIdx.x;
    const int tx = tid & 15, ty = tid >> 4;
    float acc[8][4] = {};

    for (int k0 = 0; k0 < kTotal; k0 += 16) {
        #pragma unroll
        for (int i = 0; i < 2; i++) {
            int f = tid + i * 256;
            int r = f >> 2, c = (f & 3) << 2;
            float4 va = *(const float4*)(P + (size_t)(rowBase + r) * SS + k0 + c);
            Ps[c+0][r] = va.x; Ps[c+1][r] = va.y; Ps[c+2][r] = va.z; Ps[c+3][r] = va.w;
        }
        {
            int r = tid >> 4, c = (tid & 15) << 2;
            *(float4*)&Vs[r][c] = *(const float4*)(Vm + (size_t)(k0 + r) * DH + c);
        }
        __syncthreads();
        #pragma unroll
        for (int kk = 0; kk < 16; kk++) {
            float a[8], b[4];
            *(float4*)&a[0] = *(const float4*)&Ps[kk][ty*8];
            *(float4*)&a[4] = *(const float4*)&Ps[kk][ty*8+4];
            *(float4*)&b[0] = *(const float4*)&Vs[kk][tx*4];
            #pragma unroll
            for (int i = 0; i < 8; i++)
                #pragma unroll
                for (int j = 0; j < 4; j++)
                    acc[i][j] = fmaf(a[i], b[j], acc[i][j]);
        }
        __syncthreads();
    }

    const int b = bh >> 4, h = bh & 15;
    #pragma unroll
    for (int i = 0; i < 8; i++) {
        int s = rowBase + ty * 8 + i;
        #pragma unroll
        for (int j = 0; j < 4; j++)
            g_ctx[(((size_t)(b * SS + s)) << 10) + (h << 6) + tx * 4 + j] = acc[i][j];
    }
}

// ---------------------------------------------------------------------------
// Output projection: out = ctx @ Wo^T + bo, row-major [B*S, D].
// ---------------------------------------------------------------------------
__global__ void outproj_kernel(const float* __restrict__ Wo, const float* __restrict__ bo,
                               float* __restrict__ out)
{
    const int rowBase = blockIdx.y * 128;
    const int colBase = blockIdx.x * 128;
    float acc[8][8] = {};
    gemm_nt_tile(g_ctx + (size_t)rowBase * DD, DD, Wo + (size_t)colBase * DD, DD, DD, acc);

    const int tx = threadIdx.x & 15, ty = threadIdx.x >> 4;
    #pragma unroll
    for (int i = 0; i < 8; i++) {
        int m = rowBase + ty * 8 + i;
        #pragma unroll
        for (int j = 0; j < 8; j++) {
            int n = colBase + tx * 8 + j;
            out[(size_t)m * DD + n] = acc[i][j] + bo[n];
        }
    }
}

// ---------------------------------------------------------------------------
extern "C" void kernel_launch(void* const* d_in, const int* in_sizes, int n_in,
                              void* d_out, int out_size)
{
    const float* Q  = (const float*)d_in[0];
    const float* K  = (const float*)d_in[1];
    const float* V  = (const float*)d_in[2];
    // d_in[3] = attn_mask: causal triu(k=1); applied analytically, not read.
    const float* Wq = (const float*)d_in[4];
    const float* bq = (const float*)d_in[5];
    const float* Wk = (const float*)d_in[6];
    const float* bk = (const float*)d_in[7];
    const float* Wv = (const float*)d_in[8];
    const float* bv = (const float*)d_in[9];
    const float* Wo = (const float*)d_in[10];
    const float* bo = (const float*)d_in[11];

    float* out  = (float*)d_out;                       // [B,S,D]
    float* attn = out + (size_t)BB * SS * DD;          // [B,H,S,S]

    qkv_proj_kernel<<<dim3(DD/128, (BB*SS)/128, 3), 256>>>(Q, K, V, Wq, bq, Wk, bk, Wv, bv);
    score_kernel  <<<dim3(SS/128, SS/128, BB*HH), 256>>>(attn);
    softmax_kernel<<<BB*HH*SS, 256>>>(attn);
    context_kernel<<<dim3(SS/128, 1, BB*HH), 256>>>(attn);
    outproj_kernel<<<dim3(DD/128, (BB*SS)/128), 256>>>(Wo, bo, out);
}

// round 2
// speedup vs baseline: 1.0183x; 1.0183x over previous
#include <cuda_runtime.h>
#include <stdint.h>

#define BB 2
#define SS 2048
#define DD 1024
#define HH 16
#define DH 64

// Scratch: q,k,v in [B,H,S,DH], context in [B,S,H*DH]
__device__ float g_q[BB*HH*SS*DH];
__device__ float g_k[BB*HH*SS*DH];
__device__ float g_v[BB*HH*SS*DH];
__device__ float g_ctx[(size_t)BB*SS*HH*DH];

// ---------------------------------------------------------------------------
// tf32 helpers: hi = truncate-to-tf32 (exact tf32 value), lo = x - hi (exact fp32)
// 3xTF32: acc += hi_a*hi_b + lo_a*hi_b + hi_a*lo_b  (error ~2^-22)
// ---------------------------------------------------------------------------
__device__ __forceinline__ float tf32_hi(float x) {
    return __uint_as_float(__float_as_uint(x) & 0xFFFFE000u);
}
__device__ __forceinline__ float2 tf32_split(float x) {
    float h = tf32_hi(x);
    return make_float2(h, x - h);
}

#define F2U __float_as_uint

__device__ __forceinline__ void mma8(float* c,
    uint32_t a0, uint32_t a1, uint32_t a2, uint32_t a3, uint32_t b0, uint32_t b1)
{
    asm volatile(
        "mma.sync.aligned.m16n8k8.row.col.f32.tf32.tf32.f32 "
        "{%0,%1,%2,%3}, {%4,%5,%6,%7}, {%8,%9}, {%0,%1,%2,%3};\n"
        : "+f"(c[0]), "+f"(c[1]), "+f"(c[2]), "+f"(c[3])
        : "r"(a0), "r"(a1), "r"(a2), "r"(a3), "r"(b0), "r"(b1));
}

__device__ __forceinline__ void mma3(float* c, const float2 a[4], float2 b0, float2 b1)
{
    mma8(c, F2U(a[0].x), F2U(a[1].x), F2U(a[2].x), F2U(a[3].x), F2U(b0.x), F2U(b1.x));
    mma8(c, F2U(a[0].y), F2U(a[1].y), F2U(a[2].y), F2U(a[3].y), F2U(b0.x), F2U(b1.x));
    mma8(c, F2U(a[0].x), F2U(a[1].x), F2U(a[2].x), F2U(a[3].x), F2U(b0.y), F2U(b1.y));
}

// ---------------------------------------------------------------------------
// NT tensor-core core: C[128,128] += A[128,K] * B[128,K]^T (both row-major).
// 256 threads = 8 warps (4 mrow x 2 ncol); warp tile 32x64 (mt=2, nt=8).
// smem holds (hi,lo) float2 pairs: Xs[row][kslot], stride 20 float2 -> the
// fragment LDS.64 pattern (8 gid-rows x 4 tig-cols) covers all 32 banks.
// ---------------------------------------------------------------------------
__device__ __forceinline__ void gemm128x128(
    const float* __restrict__ A, int lda,
    const float* __restrict__ B, int ldb,
    int kTiles, float2 (*As)[20], float2 (*Bs)[20],
    float acc[2][8][4])
{
    const int tid  = threadIdx.x;
    const int lane = tid & 31, warp = tid >> 5;
    const int tig  = lane & 3, gid = lane >> 2;
    const int wr   = (warp & 3) * 32;
    const int wc   = (warp >> 2) * 64;
    const int fr0  = tid >> 2, fr1 = (tid + 256) >> 2;
    const int fc   = (tid & 3) << 2;

    float4 va[2], vb[2];
    va[0] = *(const float4*)(A + (size_t)fr0 * lda + fc);
    va[1] = *(const float4*)(A + (size_t)fr1 * lda + fc);
    vb[0] = *(const float4*)(B + (size_t)fr0 * ldb + fc);
    vb[1] = *(const float4*)(B + (size_t)fr1 * ldb + fc);

    for (int kt = 0; kt < kTiles; kt++) {
        {
            float2* ap0 = &As[fr0][fc]; float2* ap1 = &As[fr1][fc];
            float2* bp0 = &Bs[fr0][fc]; float2* bp1 = &Bs[fr1][fc];
            ap0[0]=tf32_split(va[0].x); ap0[1]=tf32_split(va[0].y); ap0[2]=tf32_split(va[0].z); ap0[3]=tf32_split(va[0].w);
            ap1[0]=tf32_split(va[1].x); ap1[1]=tf32_split(va[1].y); ap1[2]=tf32_split(va[1].z); ap1[3]=tf32_split(va[1].w);
            bp0[0]=tf32_split(vb[0].x); bp0[1]=tf32_split(vb[0].y); bp0[2]=tf32_split(vb[0].z); bp0[3]=tf32_split(vb[0].w);
            bp1[0]=tf32_split(vb[1].x); bp1[1]=tf32_split(vb[1].y); bp1[2]=tf32_split(vb[1].z); bp1[3]=tf32_split(vb[1].w);
        }
        __syncthreads();
        if (kt + 1 < kTiles) {
            const float* A2 = A + (kt + 1) * 16;
            const float* B2 = B + (kt + 1) * 16;
            va[0] = *(const float4*)(A2 + (size_t)fr0 * lda + fc);
            va[1] = *(const float4*)(A2 + (size_t)fr1 * lda + fc);
            vb[0] = *(const float4*)(B2 + (size_t)fr0 * ldb + fc);
            vb[1] = *(const float4*)(B2 + (size_t)fr1 * ldb + fc);
        }
        #pragma unroll
        for (int kk = 0; kk < 2; kk++) {
            const int k0 = kk * 8 + tig;
            float2 a[2][4];
            #pragma unroll
            for (int mt = 0; mt < 2; mt++) {
                const int rA = wr + mt * 16 + gid;
                a[mt][0] = As[rA][k0];
                a[mt][1] = As[rA + 8][k0];
                a[mt][2] = As[rA][k0 + 4];
                a[mt][3] = As[rA + 8][k0 + 4];
            }
            #pragma unroll
            for (int nt = 0; nt < 8; nt++) {
                const int cB = wc + nt * 8 + gid;
                float2 b0 = Bs[cB][k0];
                float2 b1 = Bs[cB][k0 + 4];
                #pragma unroll
                for (int mt = 0; mt < 2; mt++)
                    mma3(acc[mt][nt], a[mt], b0, b1);
            }
        }
        __syncthreads();
    }
}

// ---------------------------------------------------------------------------
// QKV projections: Y = X @ W^T + b, scattered to [B,H,S,DH]; q scaled by 0.125.
// ---------------------------------------------------------------------------
__global__ void qkv_proj_kernel(
    const float* __restrict__ Qin, const float* __restrict__ Kin, const float* __restrict__ Vin,
    const float* __restrict__ Wq, const float* __restrict__ bq,
    const float* __restrict__ Wk, const float* __restrict__ bk,
    const float* __restrict__ Wv, const float* __restrict__ bv)
{
    __shared__ float2 As[128][20];
    __shared__ float2 Bs[128][20];
    const int z = blockIdx.z;
    const float* X    = (z == 0) ? Qin : (z == 1) ? Kin : Vin;
    const float* W    = (z == 0) ? Wq  : (z == 1) ? Wk  : Wv;
    const float* bias = (z == 0) ? bq  : (z == 1) ? bk  : bv;
    float* outp       = (z == 0) ? g_q : (z == 1) ? g_k : g_v;
    const float scale = (z == 0) ? 0.125f : 1.0f;

    const int rowBase = blockIdx.y * 128;
    const int colBase = blockIdx.x * 128;
    float acc[2][8][4] = {};
    gemm128x128(X + (size_t)rowBase * DD, DD, W + (size_t)colBase * DD, DD, DD / 16, As, Bs, acc);

    const int lane = threadIdx.x & 31, warp = threadIdx.x >> 5;
    const int tig = lane & 3, gid = lane >> 2;
    const int wr = (warp & 3) * 32, wc = (warp >> 2) * 64;
    #pragma unroll
    for (int mt = 0; mt < 2; mt++)
        #pragma unroll
        for (int nt = 0; nt < 8; nt++) {
            int col = colBase + wc + nt * 8 + 2 * tig;
            float2 bb = *(const float2*)&bias[col];
            int h = col >> 6, dh = col & 63;
            #pragma unroll
            for (int half = 0; half < 2; half++) {
                int row = rowBase + wr + mt * 16 + gid + 8 * half;
                int b = row >> 11, s = row & (SS - 1);
                float2 w;
                w.x = (acc[mt][nt][2 * half + 0] + bb.x) * scale;
                w.y = (acc[mt][nt][2 * half + 1] + bb.y) * scale;
                *(float2*)&outp[((((size_t)b * HH + h) * SS + s) << 6) + dh] = w;
            }
        }
}

// ---------------------------------------------------------------------------
// Scores: S = q @ k^T (q pre-scaled) into attn buffer. Upper blocks skipped.
// ---------------------------------------------------------------------------
__global__ void score_kernel(float* __restrict__ scores)
{
    if (blockIdx.x > blockIdx.y) return;
    __shared__ float2 As[128][20];
    __shared__ float2 Bs[128][20];
    const int bh = blockIdx.z;
    const int rowBase = blockIdx.y * 128;
    const int colBase = blockIdx.x * 128;
    const float* q  = g_q + (size_t)bh * SS * DH;
    const float* kx = g_k + (size_t)bh * SS * DH;
    float acc[2][8][4] = {};
    gemm128x128(q + (size_t)rowBase * DH, DH, kx + (size_t)colBase * DH, DH, DH / 16, As, Bs, acc);

    float* outp = scores + (size_t)bh * SS * SS;
    const int lane = threadIdx.x & 31, warp = threadIdx.x >> 5;
    const int tig = lane & 3, gid = lane >> 2;
    const int wr = (warp & 3) * 32, wc = (warp >> 2) * 64;
    #pragma unroll
    for (int mt = 0; mt < 2; mt++)
        #pragma unroll
        for (int nt = 0; nt < 8; nt++) {
            int col = colBase + wc + nt * 8 + 2 * tig;
            #pragma unroll
            for (int half = 0; half < 2; half++) {
                int row = rowBase + wr + mt * 16 + gid + 8 * half;
                float2 w;
                w.x = acc[mt][nt][2 * half + 0];
                w.y = acc[mt][nt][2 * half + 1];
                *(float2*)&outp[(size_t)row * SS + col] = w;
            }
        }
}

// ---------------------------------------------------------------------------
// Row softmax in place; masked tail (col > row) written as exact 0.
// ---------------------------------------------------------------------------
__global__ void softmax_kernel(float* __restrict__ sc)
{
    const int r = blockIdx.x;
    const int qi = r & (SS - 1);
    const int valid = qi + 1;
    float* row = sc + (size_t)r * SS;
    const int tid = threadIdx.x;
    const int warp = tid >> 5, lane = tid & 31;
    __shared__ float red[8];

    float v[8];
    float m = -3.4e38f;
    #pragma unroll
    for (int i = 0; i < 8; i++) {
        int idx = tid + i * 256;
        v[i] = -3.4e38f;
        if (idx < valid) { v[i] = row[idx]; m = fmaxf(m, v[i]); }
    }
    #pragma unroll
    for (int o = 16; o > 0; o >>= 1) m = fmaxf(m, __shfl_xor_sync(0xffffffffu, m, o));
    if (lane == 0) red[warp] = m;
    __syncthreads();
    float mm = (lane < 8) ? red[lane] : -3.4e38f;
    #pragma unroll
    for (int o = 4; o > 0; o >>= 1) mm = fmaxf(mm, __shfl_xor_sync(0xffffffffu, mm, o));
    mm = __shfl_sync(0xffffffffu, mm, 0);
    __syncthreads();

    float s = 0.f;
    #pragma unroll
    for (int i = 0; i < 8; i++) {
        int idx = tid + i * 256;
        if (idx < valid) { v[i] = __expf(v[i] - mm); s += v[i]; }
    }
    #pragma unroll
    for (int o = 16; o > 0; o >>= 1) s += __shfl_xor_sync(0xffffffffu, s, o);
    if (lane == 0) red[warp] = s;
    __syncthreads();
    float ss = (lane < 8) ? red[lane] : 0.f;
    #pragma unroll
    for (int o = 4; o > 0; o >>= 1) ss += __shfl_xor_sync(0xffffffffu, ss, o);
    ss = __shfl_sync(0xffffffffu, ss, 0);

    const float inv = 1.0f / ss;
    #pragma unroll
    for (int i = 0; i < 8; i++) {
        int idx = tid + i * 256;
        row[idx] = (idx < valid) ? v[i] * inv : 0.0f;
    }
}

// ---------------------------------------------------------------------------
// Context: C[128,64] = P[128,K] @ V[K,64]; causal -> K loop stops at rowBase+128.
// 8 warps, each owns 16 rows x 64 cols (mt=1, nt=8).
// ---------------------------------------------------------------------------
__global__ void context_kernel(const float* __restrict__ scores)
{
    __shared__ float2 Ps[128][20];
    __shared__ float2 Vs[16][66];
    const int bh = blockIdx.z;
    const int rowBase = blockIdx.x * 128;
    const float* P  = scores + (size_t)bh * SS * SS + (size_t)rowBase * SS;
    const float* Vm = g_v + (size_t)bh * SS * DH;
    const int kTiles = (rowBase + 128) / 16;

    const int tid = threadIdx.x, lane = tid & 31, warp = tid >> 5;
    const int tig = lane & 3, gid = lane >> 2;
    const int fr0 = tid >> 2, fr1 = (tid + 256) >> 2;
    const int fc  = (tid & 3) << 2;
    const int vkr = tid >> 4, vc = (tid & 15) << 2;

    float acc[8][4] = {};
    float4 va[2], vv;
    va[0] = *(const float4*)(P + (size_t)fr0 * SS + fc);
    va[1] = *(const float4*)(P + (size_t)fr1 * SS + fc);
    vv    = *(const float4*)(Vm + (size_t)vkr * DH + vc);

    for (int kt = 0; kt < kTiles; kt++) {
        {
            float2* p0 = &Ps[fr0][fc]; float2* p1 = &Ps[fr1][fc];
            p0[0]=tf32_split(va[0].x); p0[1]=tf32_split(va[0].y); p0[2]=tf32_split(va[0].z); p0[3]=tf32_split(va[0].w);
            p1[0]=tf32_split(va[1].x); p1[1]=tf32_split(va[1].y); p1[2]=tf32_split(va[1].z); p1[3]=tf32_split(va[1].w);
            float2* vp = &Vs[vkr][vc];
            vp[0]=tf32_split(vv.x); vp[1]=tf32_split(vv.y); vp[2]=tf32_split(vv.z); vp[3]=tf32_split(vv.w);
        }
        __syncthreads();
        if (kt + 1 < kTiles) {
            const float* P2 = P + (kt + 1) * 16;
            va[0] = *(const float4*)(P2 + (size_t)fr0 * SS + fc);
            va[1] = *(const float4*)(P2 + (size_t)fr1 * SS + fc);
            vv    = *(const float4*)(Vm + (size_t)((kt + 1) * 16 + vkr) * DH + vc);
        }
        #pragma unroll
        for (int kk = 0; kk < 2; kk++) {
            const int k0 = kk * 8 + tig;
            float2 a[4];
            const int rA = warp * 16 + gid;
            a[0] = Ps[rA][k0];
            a[1] = Ps[rA + 8][k0];
            a[2] = Ps[rA][k0 + 4];
            a[3] = Ps[rA + 8][k0 + 4];
            #pragma unroll
            for (int nt = 0; nt < 8; nt++) {
                const int cB = nt * 8 + gid;
                float2 b0 = Vs[k0][cB];
                float2 b1 = Vs[k0 + 4][cB];
                mma3(acc[nt], a, b0, b1);
            }
        }
        __syncthreads();
    }

    const int b = bh >> 4, h = bh & 15;
    #pragma unroll
    for (int nt = 0; nt < 8; nt++) {
        int col = nt * 8 + 2 * tig;
        #pragma unroll
        for (int half = 0; half < 2; half++) {
            int s = rowBase + warp * 16 + gid + 8 * half;
            float2 w;
            w.x = acc[nt][2 * half + 0];
            w.y = acc[nt][2 * half + 1];
            *(float2*)&g_ctx[((size_t)(b * SS + s) << 10) + (h << 6) + col] = w;
        }
    }
}

// ---------------------------------------------------------------------------
// Output projection: out = ctx @ Wo^T + bo.
// ---------------------------------------------------------------------------
__global__ void outproj_kernel(const float* __restrict__ Wo, const float* __restrict__ bo,
                               float* __restrict__ out)
{
    __shared__ float2 As[128][20];
    __shared__ float2 Bs[128][20];
    const int rowBase = blockIdx.y * 128;
    const int colBase = blockIdx.x * 128;
    float acc[2][8][4] = {};
    gemm128x128(g_ctx + (size_t)rowBase * DD, DD, Wo + (size_t)colBase * DD, DD, DD / 16, As, Bs, acc);

    const int lane = threadIdx.x & 31, warp = threadIdx.x >> 5;
    const int tig = lane & 3, gid = lane >> 2;
    const int wr = (warp & 3) * 32, wc = (warp >> 2) * 64;
    #pragma unroll
    for (int mt = 0; mt < 2; mt++)
        #pragma unroll
        for (int nt = 0; nt < 8; nt++) {
            int col = colBase + wc + nt * 8 + 2 * tig;
            float2 bb = *(const float2*)&bo[col];
            #pragma unroll
            for (int half = 0; half < 2; half++) {
                int row = rowBase + wr + mt * 16 + gid + 8 * half;
                float2 w;
                w.x = acc[mt][nt][2 * half + 0] + bb.x;
                w.y = acc[mt][nt][2 * half + 1] + bb.y;
                *(float2*)&out[(size_t)row * DD + col] = w;
            }
        }
}

// ---------------------------------------------------------------------------
extern "C" void kernel_launch(void* const* d_in, const int* in_sizes, int n_in,
                              void* d_out, int out_size)
{
    const float* Q  = (const float*)d_in[0];
    const float* K  = (const float*)d_in[1];
    const float* V  = (const float*)d_in[2];
    // d_in[3] = attn_mask: causal triu(k=1); applied analytically, not read.
    const float* Wq = (const float*)d_in[4];
    const float* bq = (const float*)d_in[5];
    const float* Wk = (const float*)d_in[6];
    const float* bk = (const float*)d_in[7];
    const float* Wv = (const float*)d_in[8];
    const float* bv = (const float*)d_in[9];
    const float* Wo = (const float*)d_in[10];
    const float* bo = (const float*)d_in[11];

    float* out  = (float*)d_out;                       // [B,S,D]
    float* attn = out + (size_t)BB * SS * DD;          // [B,H,S,S]

    qkv_proj_kernel<<<dim3(DD/128, (BB*SS)/128, 3), 256>>>(Q, K, V, Wq, bq, Wk, bk, Wv, bv);
    score_kernel  <<<dim3(SS/128, SS/128, BB*HH), 256>>>(attn);
    softmax_kernel<<<BB*HH*SS, 256>>>(attn);
    context_kernel<<<dim3(SS/128, 1, BB*HH), 256>>>(attn);
    outproj_kernel<<<dim3(DD/128, (BB*SS)/128), 256>>>(Wo, bo, out);
}